// round 1
// baseline (speedup 1.0000x reference)
#include <cuda_runtime.h>
#include <cuda_bf16.h>

// ---------------------------------------------------------------------------
// PINN loss: 7-layer tanh MLP (2->256 x6 ->4).
//   out[0] = mse_bc   (bc1,bc2 @1000 pts; bc3,bc4,bc5 @5000 pts)
//   out[1] = mse_data (20000 pts vs real_data)
//   out[2] = mse_f    (PDE residual via 5-stream Taylor-mode fwd on 20000 pts)
//
// Strategy: compute-bound fp32 -> use Blackwell packed fma.rn.f32x2 (FFMA2,
// 2x fp32 rate). Even/odd-k partial sums live in the two lanes of a b64
// accumulator, so no pack instructions in the inner loop: activations come
// pre-paired from shared memory via ld.shared.v2.u64, weights are packed once
// per 8-k chunk per thread. Weights stream from L2 with a 2-deep register
// double buffer.
// ---------------------------------------------------------------------------

typedef unsigned long long u64;

__device__ __forceinline__ u64 pk2(float a, float b) {
    u64 r; asm("mov.b64 %0,{%1,%2};" : "=l"(r) : "f"(a), "f"(b)); return r;
}
__device__ __forceinline__ void fma2(u64& d, u64 a, u64 b) {
    asm("fma.rn.f32x2 %0,%1,%2,%0;" : "+l"(d) : "l"(a), "l"(b));
}
__device__ __forceinline__ float rsum(u64 v) {
    float lo, hi; asm("mov.b64 {%0,%1},%2;" : "=f"(lo), "=f"(hi) : "l"(v));
    return lo + hi;
}
__device__ __forceinline__ float tanh_f(float x) {
    float e = __expf(2.f * x);
    return 1.f - __fdividef(2.f, e + 1.f);
}

struct Params {
    const float* Wh[5];   // W1..W5 (256x256)
    const float* Bh[5];   // b1..b5
    const float* W0; const float* B0;   // 2x256
    const float* W6; const float* B6;   // 256x4
    const float* bc[5];
    const float* f1;
    const float* inp;
    const float* realv;
};

#define SROW 264           // padded row stride (floats) for h buffers

// ============================ zero kernel ==================================
__global__ void zero_kernel(float* out) {
    if (threadIdx.x < 3) out[threadIdx.x] = 0.f;
}

// ============================ forward kernel ===============================
// 37000 points: [0,1000) bc1, [1000,2000) bc2, [2000,7000) bc3,
// [7000,12000) bc4, [12000,17000) bc5, [17000,37000) input_data.
#define FTP 32
#define FWD_SMEM_FLOATS (2*FTP*SROW + 1024 + 4 + 2*FTP + 2)

__global__ __launch_bounds__(256) void fwd_kernel(Params P, float* __restrict__ out) {
    extern __shared__ float sm[];
    float* h0   = sm;
    float* h1   = sm + FTP * SROW;
    float* w6s  = sm + 2 * FTP * SROW;
    float* b6s  = w6s + 1024;
    float* xs   = b6s + 4;
    float* bins = xs + 2 * FTP;

    const int tid = threadIdx.x;
    const int j   = tid;
    const int base = blockIdx.x * FTP;

    if (tid < FTP) {
        int g = base + tid;
        int gg = g < 36999 ? g : 36999;
        const float* src; int i;
        if      (gg <  1000) { src = P.bc[0]; i = gg; }
        else if (gg <  2000) { src = P.bc[1]; i = gg - 1000; }
        else if (gg <  7000) { src = P.bc[2]; i = gg - 2000; }
        else if (gg < 12000) { src = P.bc[3]; i = gg - 7000; }
        else if (gg < 17000) { src = P.bc[4]; i = gg - 12000; }
        else                 { src = P.inp;   i = gg - 17000; }
        float2 v = ((const float2*)src)[i];
        xs[2 * tid] = v.x; xs[2 * tid + 1] = v.y;
    }
    for (int r = tid; r < 1024; r += 256) w6s[r] = P.W6[r];
    if (tid < 4) b6s[tid] = P.B6[tid];
    if (tid < 2) bins[tid] = 0.f;
    __syncthreads();

    // layer 0: 2 -> 256
    {
        float w0a = P.W0[j], w0b = P.W0[256 + j], bb = P.B0[j];
        #pragma unroll
        for (int p = 0; p < FTP; p++) {
            float a = fmaf(xs[2 * p + 1], w0b, fmaf(xs[2 * p], w0a, bb));
            h0[p * SROW + j] = tanh_f(a);
        }
    }
    __syncthreads();

    float* hin = h0; float* hout = h1;
    for (int l = 0; l < 5; l++) {
        const float* Wl = P.Wh[l] + j;
        float bj = P.Bh[l][j];
        u64 acc[FTP];
        #pragma unroll
        for (int p = 0; p < FTP; p++) acc[p] = 0ull;

        float wb[2][8];
        #pragma unroll
        for (int i = 0; i < 8; i++) wb[0][i] = Wl[i * 256];

        #pragma unroll 1
        for (int c = 0; c < 32; c++) {
            if (c < 31) {
                const float* wsrc = Wl + (c + 1) * 8 * 256;
                #pragma unroll
                for (int i = 0; i < 8; i++) wb[(c + 1) & 1][i] = wsrc[i * 256];
            }
            const float* wc = wb[c & 1];
            u64 wp0 = pk2(wc[0], wc[1]), wp1 = pk2(wc[2], wc[3]);
            u64 wp2 = pk2(wc[4], wc[5]), wp3 = pk2(wc[6], wc[7]);
            const int ko = c * 8;
            #pragma unroll
            for (int p = 0; p < FTP; p++) {
                const ulonglong2* q = (const ulonglong2*)(hin + p * SROW + ko);
                ulonglong2 v0 = q[0], v1 = q[1];
                fma2(acc[p], v0.x, wp0); fma2(acc[p], v0.y, wp1);
                fma2(acc[p], v1.x, wp2); fma2(acc[p], v1.y, wp3);
            }
        }
        #pragma unroll
        for (int p = 0; p < FTP; p++)
            hout[p * SROW + j] = tanh_f(rsum(acc[p]) + bj);
        __syncthreads();
        float* t = hin; hin = hout; hout = t;
    }

    // final layer 256 -> 4 + loss
    if (tid < FTP * 4) {
        int p = tid >> 2, c = tid & 3;
        const float* hs = hin + p * SROW;
        float o = b6s[c];
        int st = (tid & 31) * 9;
        for (int kk = 0; kk < 256; kk++) {
            int k = (kk + st) & 255;
            o = fmaf(hs[k], w6s[k * 4 + c], o);
        }
        int g = base + p;
        if (g < 37000) {
            if (g < 17000) {
                float sc; bool use; float tgt = 0.f;
                if      (g <  2000) { sc = 0.001f;  use = (c < 3); }
                else if (g <  7000) { sc = 0.0002f; use = (c < 3); if (c == 1) tgt = 1.f; }
                else if (g < 12000) { sc = 0.0002f; use = (c < 3); }
                else                { sc = 0.0002f; use = (c == 3); }
                if (use) { float d = o - tgt; atomicAdd(&bins[0], d * d * sc); }
            } else {
                float d = o - P.realv[(g - 17000) * 4 + c];
                atomicAdd(&bins[1], d * d * (1.f / 80000.f));
            }
        }
    }
    __syncthreads();
    if (tid == 0) { atomicAdd(&out[0], bins[0]); atomicAdd(&out[1], bins[1]); }
}

// ============================ PDE kernel ===================================
// 5 Taylor streams (P, Z, R, ZZ, RR) propagated together through each layer.
#define PTP 8
#define PDE_SMEM_FLOATS (10*PTP*SROW + 1024 + 4 + 2*PTP + PTP*20 + 1)

__global__ __launch_bounds__(256) void pde_kernel(Params P, float* __restrict__ out) {
    extern __shared__ float sm[];
    float* bufs = sm;                               // 10 * PTP * SROW
    float* w6s  = sm + 10 * PTP * SROW;
    float* b6s  = w6s + 1024;
    float* xs   = b6s + 4;                          // 2*PTP
    float* outv = xs + 2 * PTP;                     // PTP*20
    float* bin  = outv + PTP * 20;                  // 1

    const int tid = threadIdx.x;
    const int j   = tid;
    const int base = blockIdx.x * PTP;

#define BUF(s, par) (bufs + (((s) * 2 + (par)) * PTP * SROW))

    if (tid < PTP) {
        float2 v = ((const float2*)P.f1)[base + tid];
        xs[2 * tid] = v.x; xs[2 * tid + 1] = v.y;
    }
    for (int r = tid; r < 1024; r += 256) w6s[r] = P.W6[r];
    if (tid < 4) b6s[tid] = P.B6[tid];
    if (tid == 0) bin[0] = 0.f;
    __syncthreads();

    // layer 0: input streams. h=x, hz=(1,0), hr=(0,1), hzz=hrr=0.
    {
        float w0z = P.W0[j], w0r = P.W0[256 + j], bb = P.B0[j];
        float* hP  = BUF(0, 0); float* hZ  = BUF(1, 0); float* hR  = BUF(2, 0);
        float* hZZ = BUF(3, 0); float* hRR = BUF(4, 0);
        #pragma unroll
        for (int p = 0; p < PTP; p++) {
            float z = xs[2 * p], r = xs[2 * p + 1];
            float a = fmaf(r, w0r, fmaf(z, w0z, bb));
            float t = tanh_f(a);
            float g = 1.f - t * t;
            float gg = -2.f * t * g;
            hP [p * SROW + j] = t;
            hZ [p * SROW + j] = g * w0z;
            hR [p * SROW + j] = g * w0r;
            hZZ[p * SROW + j] = gg * w0z * w0z;
            hRR[p * SROW + j] = gg * w0r * w0r;
        }
    }
    __syncthreads();

    int par = 0;
    for (int l = 0; l < 5; l++) {
        const float* Wl = P.Wh[l] + j;
        float bj = P.Bh[l][j];
        u64 aP[PTP], aZ[PTP], aR[PTP], aZ2[PTP], aR2[PTP];
        #pragma unroll
        for (int p = 0; p < PTP; p++) { aP[p]=0ull; aZ[p]=0ull; aR[p]=0ull; aZ2[p]=0ull; aR2[p]=0ull; }

        const float* hPi  = BUF(0, par); const float* hZi  = BUF(1, par);
        const float* hRi  = BUF(2, par); const float* hZ2i = BUF(3, par);
        const float* hR2i = BUF(4, par);

        float wb[2][8];
        #pragma unroll
        for (int i = 0; i < 8; i++) wb[0][i] = Wl[i * 256];

        #pragma unroll 1
        for (int c = 0; c < 32; c++) {
            if (c < 31) {
                const float* wsrc = Wl + (c + 1) * 8 * 256;
                #pragma unroll
                for (int i = 0; i < 8; i++) wb[(c + 1) & 1][i] = wsrc[i * 256];
            }
            const float* wc = wb[c & 1];
            u64 wp0 = pk2(wc[0], wc[1]), wp1 = pk2(wc[2], wc[3]);
            u64 wp2 = pk2(wc[4], wc[5]), wp3 = pk2(wc[6], wc[7]);
            const int ko = c * 8;
            #pragma unroll
            for (int p = 0; p < PTP; p++) {
                const int off = p * SROW + ko;
                { const ulonglong2* q = (const ulonglong2*)(hPi  + off); ulonglong2 v0=q[0], v1=q[1];
                  fma2(aP[p],  v0.x, wp0); fma2(aP[p],  v0.y, wp1); fma2(aP[p],  v1.x, wp2); fma2(aP[p],  v1.y, wp3); }
                { const ulonglong2* q = (const ulonglong2*)(hZi  + off); ulonglong2 v0=q[0], v1=q[1];
                  fma2(aZ[p],  v0.x, wp0); fma2(aZ[p],  v0.y, wp1); fma2(aZ[p],  v1.x, wp2); fma2(aZ[p],  v1.y, wp3); }
                { const ulonglong2* q = (const ulonglong2*)(hRi  + off); ulonglong2 v0=q[0], v1=q[1];
                  fma2(aR[p],  v0.x, wp0); fma2(aR[p],  v0.y, wp1); fma2(aR[p],  v1.x, wp2); fma2(aR[p],  v1.y, wp3); }
                { const ulonglong2* q = (const ulonglong2*)(hZ2i + off); ulonglong2 v0=q[0], v1=q[1];
                  fma2(aZ2[p], v0.x, wp0); fma2(aZ2[p], v0.y, wp1); fma2(aZ2[p], v1.x, wp2); fma2(aZ2[p], v1.y, wp3); }
                { const ulonglong2* q = (const ulonglong2*)(hR2i + off); ulonglong2 v0=q[0], v1=q[1];
                  fma2(aR2[p], v0.x, wp0); fma2(aR2[p], v0.y, wp1); fma2(aR2[p], v1.x, wp2); fma2(aR2[p], v1.y, wp3); }
            }
        }

        const int np = par ^ 1;
        float* hPo  = BUF(0, np); float* hZo  = BUF(1, np); float* hRo  = BUF(2, np);
        float* hZ2o = BUF(3, np); float* hR2o = BUF(4, np);
        #pragma unroll
        for (int p = 0; p < PTP; p++) {
            float a   = rsum(aP[p]) + bj;
            float az  = rsum(aZ[p]);
            float ar  = rsum(aR[p]);
            float azz = rsum(aZ2[p]);
            float arr = rsum(aR2[p]);
            float t = tanh_f(a);
            float g = 1.f - t * t;
            float gg = -2.f * t * g;
            hPo [p * SROW + j] = t;
            hZo [p * SROW + j] = g * az;
            hRo [p * SROW + j] = g * ar;
            hZ2o[p * SROW + j] = fmaf(gg * az, az, g * azz);
            hR2o[p * SROW + j] = fmaf(gg * ar, ar, g * arr);
        }
        __syncthreads();
        par = np;
    }

    // final layer 256 -> 4 for all 5 streams
    if (tid < PTP * 20) {
        int p = tid / 20; int rem = tid % 20; int s = rem >> 2; int c = rem & 3;
        const float* hs = BUF(s, par) + p * SROW;
        float o = (s == 0) ? b6s[c] : 0.f;
        int st = (tid & 31) * 9;
        for (int kk = 0; kk < 256; kk++) {
            int k = (kk + st) & 255;
            o = fmaf(hs[k], w6s[k * 4 + c], o);
        }
        outv[p * 20 + s * 4 + c] = o;
    }
    __syncthreads();

    if (tid < PTP) {
        int p = tid;
        float r = xs[2 * p + 1];
        const float* ov = outv + p * 20;
        float uz = ov[0],  us = ov[1],  ur = ov[2];
        float uz_z = ov[4], us_z = ov[5], ur_z = ov[6], p_z = ov[7];
        float uz_r = ov[8], us_r = ov[9], ur_r = ov[10], p_r = ov[11];
        float uz_zz = ov[12], us_zz = ov[13], ur_zz = ov[14];
        float uz_rr = ov[16], us_rr = ov[17], ur_rr = ov[18];
        const float NUc = 8e-4f;   // 1e-6 / (0.025*0.05)
        float inr = 1.f / r;
        float e1 = ur*ur_r + uz*ur_z - us*us*inr + p_r
                 - NUc*inr*ur_r - NUc*ur_rr - NUc*ur_zz + NUc*ur*inr*inr;
        float e2 = ur*us_r + uz*us_z + ur*us*inr
                 - NUc*inr*us_r - NUc*us_rr - NUc*us_zz + NUc*us*inr*inr;
        float e3 = ur*uz_r + uz*uz_z + p_z
                 - NUc*inr*uz_r - NUc*uz_rr - NUc*uz_zz;
        float e4 = ur + r*ur_r + r*uz_z;
        float v = (e1*e1 + e2*e2 + e3*e3 + e4*e4) * (1.f / 80000.f);
        atomicAdd(bin, v);
    }
    __syncthreads();
    if (tid == 0) atomicAdd(&out[2], bin[0]);
#undef BUF
}

// ============================ launcher =====================================
extern "C" void kernel_launch(void* const* d_in, const int* in_sizes, int n_in,
                              void* d_out, int out_size) {
    const float* const* din = (const float* const*)d_in;
    Params P;
    P.W0 = din[0];  P.B0 = din[1];
    P.Wh[0] = din[2];  P.Bh[0] = din[3];
    P.Wh[1] = din[4];  P.Bh[1] = din[5];
    P.Wh[2] = din[6];  P.Bh[2] = din[7];
    P.Wh[3] = din[8];  P.Bh[3] = din[9];
    P.Wh[4] = din[10]; P.Bh[4] = din[11];
    P.W6 = din[12]; P.B6 = din[13];
    P.bc[0] = din[14]; P.bc[1] = din[15]; P.bc[2] = din[16];
    P.bc[3] = din[17]; P.bc[4] = din[18];
    P.f1 = din[19]; P.inp = din[20]; P.realv = din[21];

    float* out = (float*)d_out;

    const int fwd_smem = FWD_SMEM_FLOATS * 4;
    const int pde_smem = PDE_SMEM_FLOATS * 4;
    cudaFuncSetAttribute(fwd_kernel, cudaFuncAttributeMaxDynamicSharedMemorySize, fwd_smem);
    cudaFuncSetAttribute(pde_kernel, cudaFuncAttributeMaxDynamicSharedMemorySize, pde_smem);

    zero_kernel<<<1, 32>>>(out);
    fwd_kernel<<<(37000 + FTP - 1) / FTP, 256, fwd_smem>>>(P, out);
    pde_kernel<<<20000 / PTP, 256, pde_smem>>>(P, out);
}